// round 12
// baseline (speedup 1.0000x reference)
#include <cuda_runtime.h>
#include <cstdint>

#define BB 512
#define SS 4096
#define DD 128
#define KK 409
#define VV 6
#define NT 256
#define HALF 2048

// -------- global scratch (plain overwrites / tie-path only counter) --------
__device__ float g_sc  [VV];
__device__ float g_U   [VV][64];        // U[v][n] = att_v . C1[:,n]
__device__ int   g_selT[BB][2][VV];     // tie path only
__device__ int   g_arr [BB];            // tie path only; self-resetting

// ===========================================================================
// K1: 12 CTAs. blocks 0..5 -> score MLP per class; 6..11 -> attention+U.
// ===========================================================================
__global__ void __launch_bounds__(NT)
k1_tables(const float* __restrict__ emb,
          const float* __restrict__ W1, const float* __restrict__ b1,
          const float* __restrict__ W2, const float* __restrict__ b2,
          const float* __restrict__ W3, const float* __restrict__ b3,
          const float* __restrict__ A1, const float* __restrict__ a1,
          const float* __restrict__ A2, const float* __restrict__ a2,
          const float* __restrict__ C1) {
    const int tid = threadIdx.x;
    const int bid = blockIdx.x;
    __shared__ float e_s[DD];
    __shared__ float h1_s[64];
    __shared__ float h2_s[32];
    __shared__ float att_s[DD];

    const int v = (bid < VV) ? bid : bid - VV;
    if (tid < DD) e_s[tid] = emb[v * DD + tid];
    __syncthreads();

    if (bid < VV) {
        {   // h1: 4 threads/neuron, 8-way ILP
            const int n = tid >> 2, q = tid & 3;
            const int i0 = q * 32;
            float acc[8] = {0, 0, 0, 0, 0, 0, 0, 0};
            #pragma unroll
            for (int m = 0; m < 4; m++)
                #pragma unroll
                for (int j = 0; j < 8; j++) {
                    const int i = i0 + m * 8 + j;
                    acc[j] = fmaf(e_s[i], W1[i * 64 + n], acc[j]);
                }
            float s = ((acc[0] + acc[1]) + (acc[2] + acc[3]))
                    + ((acc[4] + acc[5]) + (acc[6] + acc[7]));
            s += __shfl_down_sync(0xFFFFFFFFu, s, 2);
            s += __shfl_down_sync(0xFFFFFFFFu, s, 1);
            if (q == 0) h1_s[n] = fmaxf(s + b1[n], 0.f);
        }
        __syncthreads();
        {   // h2: 8 threads/neuron
            const int n = tid >> 3, r = tid & 7;
            float acc[8];
            #pragma unroll
            for (int j = 0; j < 8; j++) {
                const int i = r + 8 * j;
                acc[j] = h1_s[i] * W2[i * 32 + n];
            }
            float s = ((acc[0] + acc[1]) + (acc[2] + acc[3]))
                    + ((acc[4] + acc[5]) + (acc[6] + acc[7]));
            s += __shfl_down_sync(0xFFFFFFFFu, s, 4);
            s += __shfl_down_sync(0xFFFFFFFFu, s, 2);
            s += __shfl_down_sync(0xFFFFFFFFu, s, 1);
            if (r == 0) h2_s[n] = fmaxf(s + b2[n], 0.f);
        }
        __syncthreads();
        if (tid < 32) {
            float s = h2_s[tid] * W3[tid];
            #pragma unroll
            for (int o = 16; o; o >>= 1) s += __shfl_down_sync(0xFFFFFFFFu, s, o);
            if (tid == 0) g_sc[v] = 1.f / (1.f + expf(-(s + b3[0])));
        }
    } else {
        {   // g: 4 threads/neuron
            const int n = tid >> 2, q = tid & 3;
            const int i0 = q * 32;
            float acc[8] = {0, 0, 0, 0, 0, 0, 0, 0};
            #pragma unroll
            for (int m = 0; m < 4; m++)
                #pragma unroll
                for (int j = 0; j < 8; j++) {
                    const int i = i0 + m * 8 + j;
                    acc[j] = fmaf(e_s[i], A1[i * 64 + n], acc[j]);
                }
            float s = ((acc[0] + acc[1]) + (acc[2] + acc[3]))
                    + ((acc[4] + acc[5]) + (acc[6] + acc[7]));
            s += __shfl_down_sync(0xFFFFFFFFu, s, 2);
            s += __shfl_down_sync(0xFFFFFFFFu, s, 1);
            if (q == 0) h1_s[n] = fmaxf(s + a1[n], 0.f);
        }
        __syncthreads();
        {   // att: 2 threads per output dim
            const int d = tid >> 1, q = tid & 1;
            const int j0 = q * 32;
            float acc[8] = {0, 0, 0, 0, 0, 0, 0, 0};
            #pragma unroll
            for (int m = 0; m < 4; m++)
                #pragma unroll
                for (int jj = 0; jj < 8; jj++) {
                    const int j = j0 + m * 8 + jj;
                    acc[jj] = fmaf(h1_s[j], A2[j * DD + d], acc[jj]);
                }
            float s = ((acc[0] + acc[1]) + (acc[2] + acc[3]))
                    + ((acc[4] + acc[5]) + (acc[6] + acc[7]));
            s += __shfl_down_sync(0xFFFFFFFFu, s, 1);
            if (q == 0) att_s[d] = s + a2[d];
        }
        __syncthreads();
        {   // U[v][n] = att . C1[:,n]
            const int n = tid >> 2, q = tid & 3;
            const int i0 = q * 32;
            float acc[8] = {0, 0, 0, 0, 0, 0, 0, 0};
            #pragma unroll
            for (int m = 0; m < 4; m++)
                #pragma unroll
                for (int j = 0; j < 8; j++) {
                    const int i = i0 + m * 8 + j;
                    acc[j] = fmaf(att_s[i], C1[i * 64 + n], acc[j]);
                }
            float s = ((acc[0] + acc[1]) + (acc[2] + acc[3]))
                    + ((acc[4] + acc[5]) + (acc[6] + acc[7]));
            s += __shfl_down_sync(0xFFFFFFFFu, s, 2);
            s += __shfl_down_sync(0xFFFFFFFFu, s, 1);
            if (q == 0) g_U[v][n] = s;
        }
    }
}

// ===========================================================================
// K2: 2 CTAs per row (grid 1024). Each CTA scans/scatters its 2048-token
// half and redundantly COUNTS the other half (L2-hot). Warp w owns 256
// own-half tokens as 2 coalesced groups of 128.
// ===========================================================================
__global__ void __launch_bounds__(NT)
k2_half(const int* __restrict__ x,
        const float* __restrict__ c1, const float* __restrict__ C2,
        const float* __restrict__ c2, float* __restrict__ out) {
    const int row = blockIdx.x >> 1, h = blockIdx.x & 1;
    const int tid = threadIdx.x;
    const int w = tid >> 5, lane = tid & 31;

    __shared__ float sc_s[8];
    __shared__ unsigned long long wtot_s[8];   // own-half per-warp packed totals
    __shared__ unsigned long long wo_s[8];     // other-half per-warp packed counts
    __shared__ float scf[VV];
    __shared__ int   selcnt_sm[VV];
    __shared__ int   tie_sm;
    __shared__ float part[2];

    float* __restrict__ top_out = out + BB;
    float* __restrict__ fs_out  = out + BB + (size_t)BB * KK;

    if (tid < VV) { sc_s[tid] = g_sc[tid]; selcnt_sm[tid] = 0; }

    // ---- own half: 2 coalesced int4 groups (warp-blocked) ----
    const int4* rowp = reinterpret_cast<const int4*>(x + (size_t)row * SS + (size_t)h * HALF)
                     + w * 64 + lane;
    const int4 t0 = rowp[0];
    const int4 t1 = rowp[32];

    // ---- other half: 2 linear coalesced int4 loads (count only) ----
    const int4* othp = reinterpret_cast<const int4*>(x + (size_t)row * SS + (size_t)(1 - h) * HALF);
    const int4 o0 = othp[tid];
    const int4 o1 = othp[tid + NT];

    // packed counters (10 bits/class; per-warp max 256 fits)
    unsigned long long c0 = (1ULL << (10 * t0.x)) + (1ULL << (10 * t0.y))
                          + (1ULL << (10 * t0.z)) + (1ULL << (10 * t0.w));
    unsigned long long c1p = (1ULL << (10 * t1.x)) + (1ULL << (10 * t1.y))
                           + (1ULL << (10 * t1.z)) + (1ULL << (10 * t1.w));
    unsigned long long co = (1ULL << (10 * o0.x)) + (1ULL << (10 * o0.y))
                          + (1ULL << (10 * o0.z)) + (1ULL << (10 * o0.w))
                          + (1ULL << (10 * o1.x)) + (1ULL << (10 * o1.y))
                          + (1ULL << (10 * o1.z)) + (1ULL << (10 * o1.w));

    // other-half warp reduction
    #pragma unroll
    for (int o = 16; o; o >>= 1) co += __shfl_down_sync(0xFFFFFFFFu, co, o);

    // own-half interleaved inclusive scans
    unsigned long long i0 = c0, i1 = c1p;
    #pragma unroll
    for (int off = 1; off < 32; off <<= 1) {
        const unsigned long long n0 = __shfl_up_sync(0xFFFFFFFFu, i0, off);
        const unsigned long long n1 = __shfl_up_sync(0xFFFFFFFFu, i1, off);
        if (lane >= off) { i0 += n0; i1 += n1; }
    }
    const unsigned long long g0t = __shfl_sync(0xFFFFFFFFu, i0, 31);
    unsigned long long E0 = i0 - c0;
    unsigned long long E1 = (i1 - c1p) + g0t;

    if (lane == 31) wtot_s[w] = i0 + i1;
    if (lane == 0)  wo_s[w] = co;
    __syncthreads();

    // ---- lanes 0..5 (every warp): int totals (no 10-bit overflow) ----
    int T = 0, wpre = 0, O = 0, b = 0; unsigned m = 0;
    if (lane < VV) {
        #pragma unroll
        for (int i = 0; i < 8; i++) {
            const int e = (int)((wtot_s[i] >> (10 * lane)) & 1023ULL);
            T += e;
            if (i < w) wpre += e;
            O += (int)((wo_s[i] >> (10 * lane)) & 1023ULL);
        }
        const float sv = sc_s[lane];
        #pragma unroll
        for (int u = 0; u < VV; u++) {
            const int tu = __shfl_sync(0x3Fu, T + O, u);
            const float su = sc_s[u];
            if (su > sv) b += tu;
            if (su == sv) m |= 1u << u;
        }
    }
    const bool tie =
        __ballot_sync(0xFFFFFFFFu, (lane < VV) && (m != (1u << lane))) != 0;
    const int pre = (h ? O : 0) + wpre;     // earlier-token count outside warp
    const int B = b + pre;                  // fast-path combined base

    // ---- final_scores writes (LUT, 2 coalesced float4 per thread) ----
    {
        float4* fo = reinterpret_cast<float4*>(fs_out + (size_t)row * SS + (size_t)h * HALF)
                   + w * 64 + lane;
        float4 f;
        f.x = sc_s[t0.x]; f.y = sc_s[t0.y]; f.z = sc_s[t0.z]; f.w = sc_s[t0.w]; fo[0]  = f;
        f.x = sc_s[t1.x]; f.y = sc_s[t1.y]; f.z = sc_s[t1.z]; f.w = sc_s[t1.w]; fo[32] = f;
    }

    const size_t obase = (size_t)row * KK;
    const int p0 = h * HALF + w * 256 + lane * 4;

    if (!tie) {
        // ---- fast path: register-only ranked scatter ----
        #pragma unroll
        for (int g = 0; g < 2; g++) {
            const int4 t = g ? t1 : t0;
            unsigned long long& E = g ? E1 : E0;
            const int tk[4] = {t.x, t.y, t.z, t.w};
            #pragma unroll
            for (int j = 0; j < 4; j++) {
                const int v = tk[j];
                const int r = __shfl_sync(0xFFFFFFFFu, B, v)
                            + (int)((E >> (10 * v)) & 1023ULL);
                E += 1ULL << (10 * v);
                if (r < KK) top_out[obase + r] = (float)(p0 + g * 128 + j);
            }
        }
        if (h) return;                       // h=1 CTA done
        // analytic selected counts (contiguous class ranges, no ties)
        if (w == 0 && lane < VV) {
            int sel = KK - b;
            const int tot = T + O;
            sel = sel < 0 ? 0 : (sel > tot ? tot : sel);
            scf[lane] = (float)sel;
        }
        __syncthreads();
    } else {
        // ---- tie path: exact lax.top_k mask semantics (dead in practice) ----
        int ls[VV] = {0, 0, 0, 0, 0, 0};
        #pragma unroll
        for (int g = 0; g < 2; g++) {
            const int4 t = g ? t1 : t0;
            unsigned long long& E = g ? E1 : E0;
            const int tk[4] = {t.x, t.y, t.z, t.w};
            #pragma unroll
            for (int j = 0; j < 4; j++) {
                const int v = tk[j];
                const unsigned mv = __shfl_sync(0xFFFFFFFFu, m, v);
                int r = __shfl_sync(0xFFFFFFFFu, b, v);
                #pragma unroll
                for (int u = 0; u < VV; u++)
                    if ((mv >> u) & 1u)
                        r += __shfl_sync(0xFFFFFFFFu, pre, u)
                           + (int)((E >> (10 * u)) & 1023ULL);
                E += 1ULL << (10 * v);
                if (r < KK) {
                    top_out[obase + r] = (float)(p0 + g * 128 + j);
                    #pragma unroll
                    for (int u = 0; u < VV; u++) ls[u] += (v == u);
                }
            }
        }
        #pragma unroll
        for (int u = 0; u < VV; u++) {
            #pragma unroll
            for (int o = 16; o; o >>= 1) ls[u] += __shfl_down_sync(0xFFFFFFFFu, ls[u], o);
        }
        if (lane == 0) {
            #pragma unroll
            for (int u = 0; u < VV; u++)
                if (ls[u]) atomicAdd(&selcnt_sm[u], ls[u]);
        }
        __syncthreads();
        // publish this half's counts; last CTA of the row does the tail
        if (tid < VV) g_selT[row][h][tid] = selcnt_sm[tid];
        __syncthreads();
        if (tid == 0) {
            __threadfence();
            tie_sm = (atomicAdd(&g_arr[row], 1) == 1);
        }
        __syncthreads();
        if (!tie_sm) return;
        __threadfence();
        if (tid == 0) g_arr[row] = 0;
        if (tid < VV) scf[tid] = (float)(g_selT[row][0][tid] + g_selT[row][1][tid]);
        __syncthreads();
    }

    // ---- classifier tail: h_n = relu(sum_v (cnt_v/K) U[v][n] + c1_n) ----
    if (tid < 64) {
        const float inv = 1.0f / (float)KK;
        float acc = c1[tid];
        #pragma unroll
        for (int v = 0; v < VV; v++)
            acc = fmaf(scf[v] * inv, g_U[v][tid], acc);
        float hh = fmaxf(acc, 0.f) * C2[tid];
        #pragma unroll
        for (int o = 16; o; o >>= 1) hh += __shfl_down_sync(0xFFFFFFFFu, hh, o);
        if ((tid & 31) == 0) part[tid >> 5] = hh;
    }
    __syncthreads();
    if (tid == 0)
        out[row] = 1.f / (1.f + expf(-(part[0] + part[1] + c2[0])));
}

// ===========================================================================
extern "C" void kernel_launch(void* const* d_in, const int* in_sizes, int n_in,
                              void* d_out, int out_size) {
    const int*   x   = (const int*)  d_in[0];
    const float* emb = (const float*)d_in[1];
    const float* W1  = (const float*)d_in[2];
    const float* b1  = (const float*)d_in[3];
    const float* W2  = (const float*)d_in[4];
    const float* b2  = (const float*)d_in[5];
    const float* W3  = (const float*)d_in[6];
    const float* b3  = (const float*)d_in[7];
    const float* A1  = (const float*)d_in[8];
    const float* a1  = (const float*)d_in[9];
    const float* A2  = (const float*)d_in[10];
    const float* a2  = (const float*)d_in[11];
    const float* C1  = (const float*)d_in[12];
    const float* c1  = (const float*)d_in[13];
    const float* C2  = (const float*)d_in[14];
    const float* c2  = (const float*)d_in[15];
    float* out = (float*)d_out;

    k1_tables<<<2 * VV, NT>>>(emb, W1, b1, W2, b2, W3, b3, A1, a1, A2, a2, C1);
    k2_half<<<BB * 2, NT>>>(x, c1, C2, c2, out);
}

// round 13
// speedup vs baseline: 1.0408x; 1.0408x over previous
#include <cuda_runtime.h>
#include <cstdint>

#define BB 512
#define SS 4096
#define DD 128
#define KK 409
#define VV 6
#define NT 256
#define TBLK (2 * VV)          // 12 table CTAs, bids 0..11 (wave-1 resident)

// -------- global scratch (zero at load; self-resetting each run) --------
__device__ float g_sc [VV];
__device__ float g_U  [VV][64];    // U[v][n] = att_v . C1[:,n]
__device__ int   g_done;           // tables completed (0 -> 12 -> reset 0)
__device__ int   g_pass;           // row CTAs retired  (0 -> 512 -> reset 0)

// ===========================================================================
// Fused kernel.
//   blocks 0..5   : score MLP for class bid
//   blocks 6..11  : attention MLP + U precompute for class bid-6
//   blocks 12..523: one row each — load/count/scan (score-independent),
//                   acquire-spin on g_done, then fs writes + ranked scatter
//                   + analytic selcnt + classifier tail.
// ===========================================================================
__global__ void __launch_bounds__(NT, 4)
k_all(const int* __restrict__ x,
      const float* __restrict__ emb,
      const float* __restrict__ W1, const float* __restrict__ b1,
      const float* __restrict__ W2, const float* __restrict__ b2,
      const float* __restrict__ W3, const float* __restrict__ b3,
      const float* __restrict__ A1, const float* __restrict__ a1,
      const float* __restrict__ A2, const float* __restrict__ a2,
      const float* __restrict__ C1, const float* __restrict__ c1,
      const float* __restrict__ C2, const float* __restrict__ c2,
      float* __restrict__ out) {
    const int tid = threadIdx.x;

    if (blockIdx.x < TBLK) {
        // ================= table CTAs =================
        const int bid = blockIdx.x;
        __shared__ float e_s[DD];
        __shared__ float h1_s[64];
        __shared__ float h2_s[32];
        __shared__ float att_s[DD];

        const int v = (bid < VV) ? bid : bid - VV;
        if (tid < DD) e_s[tid] = emb[v * DD + tid];
        __syncthreads();

        if (bid < VV) {
            {   // h1: 4 threads/neuron, 8-way ILP
                const int n = tid >> 2, q = tid & 3;
                const int i0 = q * 32;
                float acc[8] = {0, 0, 0, 0, 0, 0, 0, 0};
                #pragma unroll
                for (int mm = 0; mm < 4; mm++)
                    #pragma unroll
                    for (int j = 0; j < 8; j++) {
                        const int i = i0 + mm * 8 + j;
                        acc[j] = fmaf(e_s[i], W1[i * 64 + n], acc[j]);
                    }
                float s = ((acc[0] + acc[1]) + (acc[2] + acc[3]))
                        + ((acc[4] + acc[5]) + (acc[6] + acc[7]));
                s += __shfl_down_sync(0xFFFFFFFFu, s, 2);
                s += __shfl_down_sync(0xFFFFFFFFu, s, 1);
                if (q == 0) h1_s[n] = fmaxf(s + b1[n], 0.f);
            }
            __syncthreads();
            {   // h2: 8 threads/neuron
                const int n = tid >> 3, r = tid & 7;
                float acc[8];
                #pragma unroll
                for (int j = 0; j < 8; j++) {
                    const int i = r + 8 * j;
                    acc[j] = h1_s[i] * W2[i * 32 + n];
                }
                float s = ((acc[0] + acc[1]) + (acc[2] + acc[3]))
                        + ((acc[4] + acc[5]) + (acc[6] + acc[7]));
                s += __shfl_down_sync(0xFFFFFFFFu, s, 4);
                s += __shfl_down_sync(0xFFFFFFFFu, s, 2);
                s += __shfl_down_sync(0xFFFFFFFFu, s, 1);
                if (r == 0) h2_s[n] = fmaxf(s + b2[n], 0.f);
            }
            __syncthreads();
            if (tid < 32) {
                float s = h2_s[tid] * W3[tid];
                #pragma unroll
                for (int o = 16; o; o >>= 1) s += __shfl_down_sync(0xFFFFFFFFu, s, o);
                if (tid == 0) g_sc[v] = 1.f / (1.f + expf(-(s + b3[0])));
            }
        } else {
            {   // g: 4 threads/neuron
                const int n = tid >> 2, q = tid & 3;
                const int i0 = q * 32;
                float acc[8] = {0, 0, 0, 0, 0, 0, 0, 0};
                #pragma unroll
                for (int mm = 0; mm < 4; mm++)
                    #pragma unroll
                    for (int j = 0; j < 8; j++) {
                        const int i = i0 + mm * 8 + j;
                        acc[j] = fmaf(e_s[i], A1[i * 64 + n], acc[j]);
                    }
                float s = ((acc[0] + acc[1]) + (acc[2] + acc[3]))
                        + ((acc[4] + acc[5]) + (acc[6] + acc[7]));
                s += __shfl_down_sync(0xFFFFFFFFu, s, 2);
                s += __shfl_down_sync(0xFFFFFFFFu, s, 1);
                if (q == 0) h1_s[n] = fmaxf(s + a1[n], 0.f);   // g
            }
            __syncthreads();
            {   // att: 2 threads per output dim
                const int d = tid >> 1, q = tid & 1;
                const int j0 = q * 32;
                float acc[8] = {0, 0, 0, 0, 0, 0, 0, 0};
                #pragma unroll
                for (int mm = 0; mm < 4; mm++)
                    #pragma unroll
                    for (int jj = 0; jj < 8; jj++) {
                        const int j = j0 + mm * 8 + jj;
                        acc[jj] = fmaf(h1_s[j], A2[j * DD + d], acc[jj]);
                    }
                float s = ((acc[0] + acc[1]) + (acc[2] + acc[3]))
                        + ((acc[4] + acc[5]) + (acc[6] + acc[7]));
                s += __shfl_down_sync(0xFFFFFFFFu, s, 1);
                if (q == 0) att_s[d] = s + a2[d];
            }
            __syncthreads();
            {   // U[v][n] = att . C1[:,n]
                const int n = tid >> 2, q = tid & 3;
                const int i0 = q * 32;
                float acc[8] = {0, 0, 0, 0, 0, 0, 0, 0};
                #pragma unroll
                for (int mm = 0; mm < 4; mm++)
                    #pragma unroll
                    for (int j = 0; j < 8; j++) {
                        const int i = i0 + mm * 8 + j;
                        acc[j] = fmaf(att_s[i], C1[i * 64 + n], acc[j]);
                    }
                float s = ((acc[0] + acc[1]) + (acc[2] + acc[3]))
                        + ((acc[4] + acc[5]) + (acc[6] + acc[7]));
                s += __shfl_down_sync(0xFFFFFFFFu, s, 2);
                s += __shfl_down_sync(0xFFFFFFFFu, s, 1);
                if (q == 0) g_U[v][n] = s;
            }
        }
        // release: make this CTA's table writes visible, then signal
        __threadfence();
        __syncthreads();
        if (tid == 0) atomicAdd(&g_done, 1);
        return;
    }

    // ================= row CTAs =================
    const int row = blockIdx.x - TBLK;
    const int w = tid >> 5, lane = tid & 31;
    const int cls = (lane < VV) ? lane : 0;        // clamped class id

    __shared__ unsigned long long wtot_s[8];
    __shared__ int   selcnt_sm[VV];                // tie path only
    __shared__ float scf_sm[VV];                   // tie path only

    float* __restrict__ top_out = out + BB;
    float* __restrict__ fs_out  = out + BB + (size_t)BB * KK;

    // ---- 16 consecutive tokens per thread: 4 LDG.128 within own 64B span ----
    const int4* rp = reinterpret_cast<const int4*>(x + (size_t)row * SS) + tid * 4;
    const int4 t0 = rp[0];
    const int4 t1 = rp[1];
    const int4 t2 = rp[2];
    const int4 t3 = rp[3];

    // ---- packed per-thread count (10 bits/class) ----
    unsigned long long c = 0;
    c += 1ULL << (10 * t0.x); c += 1ULL << (10 * t0.y);
    c += 1ULL << (10 * t0.z); c += 1ULL << (10 * t0.w);
    c += 1ULL << (10 * t1.x); c += 1ULL << (10 * t1.y);
    c += 1ULL << (10 * t1.z); c += 1ULL << (10 * t1.w);
    c += 1ULL << (10 * t2.x); c += 1ULL << (10 * t2.y);
    c += 1ULL << (10 * t2.z); c += 1ULL << (10 * t2.w);
    c += 1ULL << (10 * t3.x); c += 1ULL << (10 * t3.y);
    c += 1ULL << (10 * t3.z); c += 1ULL << (10 * t3.w);

    // ---- single inclusive warp scan (lane-major == position order) ----
    unsigned long long incl = c;
    #pragma unroll
    for (int off = 1; off < 32; off <<= 1) {
        const unsigned long long n = __shfl_up_sync(0xFFFFFFFFu, incl, off);
        if (lane >= off) incl += n;
    }
    unsigned long long E = incl - c;               // exclusive in-warp prefix
    if (lane == 31) wtot_s[w] = incl;              // warp totals (packed)

    // ---- acquire-gate on table results (overlaps the DRAM read above) ----
    if (tid == 0) {
        while (*((volatile int*)&g_done) != TBLK) { }
        __threadfence();                           // acquire
    }
    __syncthreads();                               // also publishes wtot_s

    // ---- per-warp lanes: class totals, warp prefix, strict base, eq-mask ----
    int T = 0, wpre = 0;
    #pragma unroll
    for (int i = 0; i < 8; i++) {
        const int e = (int)((wtot_s[i] >> (10 * cls)) & 1023ULL);
        T += e;
        if (i < w) wpre += e;
    }
    const float scv = g_sc[cls];                   // L2-hot broadcast
    int b = 0; unsigned m = 0;
    #pragma unroll
    for (int u = 0; u < VV; u++) {
        const int   tu = __shfl_sync(0xFFFFFFFFu, T,   u);
        const float su = __shfl_sync(0xFFFFFFFFu, scv, u);
        if (su > scv) b += tu;
        if (su == scv) m |= 1u << u;
    }
    const bool tie =
        __ballot_sync(0xFFFFFFFFu, (lane < VV) && (m != (1u << lane))) != 0;
    const int B = b + wpre;                        // valid in lanes 0..5

    // ---- final_scores (LUT via shfl, 4 STG.128 in own 64B span) ----
    {
        float4* fo = reinterpret_cast<float4*>(fs_out + (size_t)row * SS) + tid * 4;
        float4 f;
        f.x = __shfl_sync(0xFFFFFFFFu, scv, t0.x);
        f.y = __shfl_sync(0xFFFFFFFFu, scv, t0.y);
        f.z = __shfl_sync(0xFFFFFFFFu, scv, t0.z);
        f.w = __shfl_sync(0xFFFFFFFFu, scv, t0.w); fo[0] = f;
        f.x = __shfl_sync(0xFFFFFFFFu, scv, t1.x);
        f.y = __shfl_sync(0xFFFFFFFFu, scv, t1.y);
        f.z = __shfl_sync(0xFFFFFFFFu, scv, t1.z);
        f.w = __shfl_sync(0xFFFFFFFFu, scv, t1.w); fo[1] = f;
        f.x = __shfl_sync(0xFFFFFFFFu, scv, t2.x);
        f.y = __shfl_sync(0xFFFFFFFFu, scv, t2.y);
        f.z = __shfl_sync(0xFFFFFFFFu, scv, t2.z);
        f.w = __shfl_sync(0xFFFFFFFFu, scv, t2.w); fo[2] = f;
        f.x = __shfl_sync(0xFFFFFFFFu, scv, t3.x);
        f.y = __shfl_sync(0xFFFFFFFFu, scv, t3.y);
        f.z = __shfl_sync(0xFFFFFFFFu, scv, t3.z);
        f.w = __shfl_sync(0xFFFFFFFFu, scv, t3.w); fo[3] = f;
    }

    const size_t obase = (size_t)row * KK;
    const int pos0 = tid * 16;

    if (!tie) {
        // ---- fast path: register-only ranked scatter, 16 consecutive tokens --
        const int tk[16] = {t0.x, t0.y, t0.z, t0.w, t1.x, t1.y, t1.z, t1.w,
                            t2.x, t2.y, t2.z, t2.w, t3.x, t3.y, t3.z, t3.w};
        #pragma unroll
        for (int j = 0; j < 16; j++) {
            const int v = tk[j];
            const int r = __shfl_sync(0xFFFFFFFFu, B, v)
                        + (int)((E >> (10 * v)) & 1023ULL);
            E += 1ULL << (10 * v);
            if (r < KK) top_out[obase + r] = (float)(pos0 + j);
        }
        // ---- warp-0 tail: analytic selcnt + classifier, barrier-free ----
        if (w == 0) {
            int sel = KK - b;
            sel = sel < 0 ? 0 : (sel > T ? T : sel);       // lanes 0..5 valid
            const float cnt = (float)sel * (1.0f / (float)KK);
            float acc0 = c1[lane], acc1 = c1[lane + 32];
            #pragma unroll
            for (int v = 0; v < VV; v++) {
                const float cv = __shfl_sync(0xFFFFFFFFu, cnt, v);
                acc0 = fmaf(cv, g_U[v][lane],      acc0);
                acc1 = fmaf(cv, g_U[v][lane + 32], acc1);
            }
            float s = fmaxf(acc0, 0.f) * C2[lane] + fmaxf(acc1, 0.f) * C2[lane + 32];
            #pragma unroll
            for (int o = 16; o; o >>= 1) s += __shfl_down_sync(0xFFFFFFFFu, s, o);
            if (lane == 0) out[row] = 1.f / (1.f + expf(-(s + c2[0])));
        }
    } else {
        // ---- tie path: exact lax.top_k mask semantics (dead in practice) ----
        if (tid < VV) selcnt_sm[tid] = 0;
        __syncthreads();
        const int tk[16] = {t0.x, t0.y, t0.z, t0.w, t1.x, t1.y, t1.z, t1.w,
                            t2.x, t2.y, t2.z, t2.w, t3.x, t3.y, t3.z, t3.w};
        int ls[VV] = {0, 0, 0, 0, 0, 0};
        #pragma unroll
        for (int j = 0; j < 16; j++) {
            const int v = tk[j];
            const unsigned mv = __shfl_sync(0xFFFFFFFFu, m, v);
            int r = __shfl_sync(0xFFFFFFFFu, b, v);
            #pragma unroll
            for (int u = 0; u < VV; u++)
                if ((mv >> u) & 1u)
                    r += __shfl_sync(0xFFFFFFFFu, wpre, u)
                       + (int)((E >> (10 * u)) & 1023ULL);
            E += 1ULL << (10 * v);
            if (r < KK) {
                top_out[obase + r] = (float)(pos0 + j);
                #pragma unroll
                for (int u = 0; u < VV; u++) ls[u] += (v == u);
            }
        }
        #pragma unroll
        for (int u = 0; u < VV; u++) {
            #pragma unroll
            for (int o = 16; o; o >>= 1) ls[u] += __shfl_down_sync(0xFFFFFFFFu, ls[u], o);
        }
        if (lane == 0) {
            #pragma unroll
            for (int u = 0; u < VV; u++)
                if (ls[u]) atomicAdd(&selcnt_sm[u], ls[u]);
        }
        __syncthreads();
        if (tid < VV) scf_sm[tid] = (float)selcnt_sm[tid];
        __syncthreads();
        if (w == 0) {
            const float cnt = scf_sm[cls] * (1.0f / (float)KK);
            float acc0 = c1[lane], acc1 = c1[lane + 32];
            #pragma unroll
            for (int v = 0; v < VV; v++) {
                const float cv = __shfl_sync(0xFFFFFFFFu, cnt, v);
                acc0 = fmaf(cv, g_U[v][lane],      acc0);
                acc1 = fmaf(cv, g_U[v][lane + 32], acc1);
            }
            float s = fmaxf(acc0, 0.f) * C2[lane] + fmaxf(acc1, 0.f) * C2[lane + 32];
            #pragma unroll
            for (int o = 16; o; o >>= 1) s += __shfl_down_sync(0xFFFFFFFFu, s, o);
            if (lane == 0) out[row] = 1.f / (1.f + expf(-(s + c2[0])));
        }
    }

    // ---- replay-reset protocol: last row CTA clears the gate counters ----
    if (tid == 0) {
        if (atomicAdd(&g_pass, 1) == BB - 1) {
            g_pass = 0;
            g_done = 0;
        }
    }
}

// ===========================================================================
extern "C" void kernel_launch(void* const* d_in, const int* in_sizes, int n_in,
                              void* d_out, int out_size) {
    const int*   x   = (const int*)  d_in[0];
    const float* emb = (const float*)d_in[1];
    const float* W1  = (const float*)d_in[2];
    const float* b1  = (const float*)d_in[3];
    const float* W2  = (const float*)d_in[4];
    const float* b2  = (const float*)d_in[5];
    const float* W3  = (const float*)d_in[6];
    const float* b3  = (const float*)d_in[7];
    const float* A1  = (const float*)d_in[8];
    const float* a1  = (const float*)d_in[9];
    const float* A2  = (const float*)d_in[10];
    const float* a2  = (const float*)d_in[11];
    const float* C1  = (const float*)d_in[12];
    const float* c1  = (const float*)d_in[13];
    const float* C2  = (const float*)d_in[14];
    const float* c2  = (const float*)d_in[15];
    float* out = (float*)d_out;

    k_all<<<TBLK + BB, NT>>>(x, emb, W1, b1, W2, b2, W3, b3,
                             A1, a1, A2, a2, C1, c1, C2, c2, out);
}

// round 14
// speedup vs baseline: 1.0469x; 1.0059x over previous
#include <cuda_runtime.h>
#include <cstdint>

#define BB 512
#define SS 4096
#define DD 128
#define KK 409
#define VV 6
#define NT 256
#define TBLK (2 * VV)          // 12 table CTAs, bids 0..11 (wave-1 resident)

// -------- global scratch (zero at load; self-resetting each run) --------
__device__ float g_sc [VV];
__device__ float g_U  [VV][64];    // U[v][n] = att_v . C1[:,n]
__device__ int   g_done;           // tables completed (0 -> 12 -> reset 0)
__device__ int   g_pass;           // row CTAs retired  (0 -> 512 -> reset 0)

// ===========================================================================
// Fused kernel.
//   blocks 0..5   : score MLP per class
//   blocks 6..11  : attention MLP + U precompute per class
//   blocks 12..523: one row each.
// Row CTA layout: warp w owns tokens [w*512,(w+1)*512) as TWO position-
// ordered 256-token segments; lane owns 8 consecutive tokens per segment
// (2 int4 loads, 32B per lane) -> 2 packed-u64 scans, nL=8 per LDG.
// ===========================================================================
__global__ void __launch_bounds__(NT, 4)
k_all(const int* __restrict__ x,
      const float* __restrict__ emb,
      const float* __restrict__ W1, const float* __restrict__ b1,
      const float* __restrict__ W2, const float* __restrict__ b2,
      const float* __restrict__ W3, const float* __restrict__ b3,
      const float* __restrict__ A1, const float* __restrict__ a1,
      const float* __restrict__ A2, const float* __restrict__ a2,
      const float* __restrict__ C1, const float* __restrict__ c1,
      const float* __restrict__ C2, const float* __restrict__ c2,
      float* __restrict__ out) {
    const int tid = threadIdx.x;

    if (blockIdx.x < TBLK) {
        // ================= table CTAs =================
        const int bid = blockIdx.x;
        __shared__ float e_s[DD];
        __shared__ float h1_s[64];
        __shared__ float h2_s[32];
        __shared__ float att_s[DD];

        const int v = (bid < VV) ? bid : bid - VV;
        if (tid < DD) e_s[tid] = emb[v * DD + tid];
        __syncthreads();

        if (bid < VV) {
            {   // h1: 4 threads/neuron, 8-way ILP
                const int n = tid >> 2, q = tid & 3;
                const int i0 = q * 32;
                float acc[8] = {0, 0, 0, 0, 0, 0, 0, 0};
                #pragma unroll
                for (int mm = 0; mm < 4; mm++)
                    #pragma unroll
                    for (int j = 0; j < 8; j++) {
                        const int i = i0 + mm * 8 + j;
                        acc[j] = fmaf(e_s[i], W1[i * 64 + n], acc[j]);
                    }
                float s = ((acc[0] + acc[1]) + (acc[2] + acc[3]))
                        + ((acc[4] + acc[5]) + (acc[6] + acc[7]));
                s += __shfl_down_sync(0xFFFFFFFFu, s, 2);
                s += __shfl_down_sync(0xFFFFFFFFu, s, 1);
                if (q == 0) h1_s[n] = fmaxf(s + b1[n], 0.f);
            }
            __syncthreads();
            {   // h2: 8 threads/neuron
                const int n = tid >> 3, r = tid & 7;
                float acc[8];
                #pragma unroll
                for (int j = 0; j < 8; j++) {
                    const int i = r + 8 * j;
                    acc[j] = h1_s[i] * W2[i * 32 + n];
                }
                float s = ((acc[0] + acc[1]) + (acc[2] + acc[3]))
                        + ((acc[4] + acc[5]) + (acc[6] + acc[7]));
                s += __shfl_down_sync(0xFFFFFFFFu, s, 4);
                s += __shfl_down_sync(0xFFFFFFFFu, s, 2);
                s += __shfl_down_sync(0xFFFFFFFFu, s, 1);
                if (r == 0) h2_s[n] = fmaxf(s + b2[n], 0.f);
            }
            __syncthreads();
            if (tid < 32) {
                float s = h2_s[tid] * W3[tid];
                #pragma unroll
                for (int o = 16; o; o >>= 1) s += __shfl_down_sync(0xFFFFFFFFu, s, o);
                if (tid == 0) g_sc[v] = 1.f / (1.f + expf(-(s + b3[0])));
            }
        } else {
            {   // g: 4 threads/neuron
                const int n = tid >> 2, q = tid & 3;
                const int i0 = q * 32;
                float acc[8] = {0, 0, 0, 0, 0, 0, 0, 0};
                #pragma unroll
                for (int mm = 0; mm < 4; mm++)
                    #pragma unroll
                    for (int j = 0; j < 8; j++) {
                        const int i = i0 + mm * 8 + j;
                        acc[j] = fmaf(e_s[i], A1[i * 64 + n], acc[j]);
                    }
                float s = ((acc[0] + acc[1]) + (acc[2] + acc[3]))
                        + ((acc[4] + acc[5]) + (acc[6] + acc[7]));
                s += __shfl_down_sync(0xFFFFFFFFu, s, 2);
                s += __shfl_down_sync(0xFFFFFFFFu, s, 1);
                if (q == 0) h1_s[n] = fmaxf(s + a1[n], 0.f);   // g
            }
            __syncthreads();
            {   // att: 2 threads per output dim
                const int d = tid >> 1, q = tid & 1;
                const int j0 = q * 32;
                float acc[8] = {0, 0, 0, 0, 0, 0, 0, 0};
                #pragma unroll
                for (int mm = 0; mm < 4; mm++)
                    #pragma unroll
                    for (int jj = 0; jj < 8; jj++) {
                        const int j = j0 + mm * 8 + jj;
                        acc[jj] = fmaf(h1_s[j], A2[j * DD + d], acc[jj]);
                    }
                float s = ((acc[0] + acc[1]) + (acc[2] + acc[3]))
                        + ((acc[4] + acc[5]) + (acc[6] + acc[7]));
                s += __shfl_down_sync(0xFFFFFFFFu, s, 1);
                if (q == 0) att_s[d] = s + a2[d];
            }
            __syncthreads();
            {   // U[v][n] = att . C1[:,n]
                const int n = tid >> 2, q = tid & 3;
                const int i0 = q * 32;
                float acc[8] = {0, 0, 0, 0, 0, 0, 0, 0};
                #pragma unroll
                for (int mm = 0; mm < 4; mm++)
                    #pragma unroll
                    for (int j = 0; j < 8; j++) {
                        const int i = i0 + mm * 8 + j;
                        acc[j] = fmaf(att_s[i], C1[i * 64 + n], acc[j]);
                    }
                float s = ((acc[0] + acc[1]) + (acc[2] + acc[3]))
                        + ((acc[4] + acc[5]) + (acc[6] + acc[7]));
                s += __shfl_down_sync(0xFFFFFFFFu, s, 2);
                s += __shfl_down_sync(0xFFFFFFFFu, s, 1);
                if (q == 0) g_U[v][n] = s;
            }
        }
        __threadfence();                // release table writes
        __syncthreads();
        if (tid == 0) atomicAdd(&g_done, 1);
        return;
    }

    // ================= row CTAs =================
    const int row = blockIdx.x - TBLK;
    const int w = tid >> 5, lane = tid & 31;
    const int cls = (lane < VV) ? lane : 0;

    __shared__ unsigned long long wtot_s[8];
    __shared__ int   selcnt_sm[VV];                // tie path only
    __shared__ float scf_sm[VV];                   // tie path only

    float* __restrict__ top_out = out + BB;
    float* __restrict__ fs_out  = out + BB + (size_t)BB * KK;

    // ---- loads: lane owns 8 consecutive tokens per segment (2 int4) ----
    // segment s of warp w starts at token w*512 + s*256; lane offset 8*lane.
    const int4* rp = reinterpret_cast<const int4*>(x + (size_t)row * SS);
    const int i0 = w * 128 + lane * 2;             // int4 index, segment 0
    const int4 a0 = rp[i0];
    const int4 a1v = rp[i0 + 1];
    const int4 b0 = rp[i0 + 64];                   // segment 1 (+256 tokens)
    const int4 b1v = rp[i0 + 65];

    // ---- packed per-thread counts (10 bits/class) ----
    unsigned long long ca = 0, cb = 0;
    ca += 1ULL << (10 * a0.x);  ca += 1ULL << (10 * a0.y);
    ca += 1ULL << (10 * a0.z);  ca += 1ULL << (10 * a0.w);
    ca += 1ULL << (10 * a1v.x); ca += 1ULL << (10 * a1v.y);
    ca += 1ULL << (10 * a1v.z); ca += 1ULL << (10 * a1v.w);
    cb += 1ULL << (10 * b0.x);  cb += 1ULL << (10 * b0.y);
    cb += 1ULL << (10 * b0.z);  cb += 1ULL << (10 * b0.w);
    cb += 1ULL << (10 * b1v.x); cb += 1ULL << (10 * b1v.y);
    cb += 1ULL << (10 * b1v.z); cb += 1ULL << (10 * b1v.w);

    // ---- 2 interleaved inclusive warp scans (position order per segment) ----
    unsigned long long ia = ca, ib = cb;
    #pragma unroll
    for (int off = 1; off < 32; off <<= 1) {
        const unsigned long long na = __shfl_up_sync(0xFFFFFFFFu, ia, off);
        const unsigned long long nb = __shfl_up_sync(0xFFFFFFFFu, ib, off);
        if (lane >= off) { ia += na; ib += nb; }
    }
    const unsigned long long seg0t = __shfl_sync(0xFFFFFFFFu, ia, 31);
    unsigned long long Ea = ia - ca;               // excl prefix, segment 0
    unsigned long long Eb = (ib - cb) + seg0t;     // excl prefix, segment 1
    if (lane == 31) wtot_s[w] = ia + ib;           // warp packed totals

    // ---- acquire-gate on table results (overlaps the DRAM read above) ----
    if (tid == 0) {
        while (*((volatile int*)&g_done) != TBLK) { }
        __threadfence();
    }
    __syncthreads();                               // also publishes wtot_s

    // ---- per-warp lanes: class totals, warp prefix, strict base, eq-mask ----
    int T = 0, wpre = 0;
    #pragma unroll
    for (int i = 0; i < 8; i++) {
        const int e = (int)((wtot_s[i] >> (10 * cls)) & 1023ULL);
        T += e;
        if (i < w) wpre += e;
    }
    const float scv = g_sc[cls];                   // L2-hot broadcast
    int b = 0; unsigned m = 0;
    #pragma unroll
    for (int u = 0; u < VV; u++) {
        const int   tu = __shfl_sync(0xFFFFFFFFu, T,   u);
        const float su = __shfl_sync(0xFFFFFFFFu, scv, u);
        if (su > scv) b += tu;
        if (su == scv) m |= 1u << u;
    }
    const bool tie =
        __ballot_sync(0xFFFFFFFFu, (lane < VV) && (m != (1u << lane))) != 0;
    const int B = b + wpre;                        // valid in lanes 0..5

    // ---- final_scores (shfl LUT, same 32B-per-lane pattern as loads) ----
    {
        float4* fo = reinterpret_cast<float4*>(fs_out + (size_t)row * SS);
        float4 f;
        f.x = __shfl_sync(0xFFFFFFFFu, scv, a0.x);
        f.y = __shfl_sync(0xFFFFFFFFu, scv, a0.y);
        f.z = __shfl_sync(0xFFFFFFFFu, scv, a0.z);
        f.w = __shfl_sync(0xFFFFFFFFu, scv, a0.w); fo[i0] = f;
        f.x = __shfl_sync(0xFFFFFFFFu, scv, a1v.x);
        f.y = __shfl_sync(0xFFFFFFFFu, scv, a1v.y);
        f.z = __shfl_sync(0xFFFFFFFFu, scv, a1v.z);
        f.w = __shfl_sync(0xFFFFFFFFu, scv, a1v.w); fo[i0 + 1] = f;
        f.x = __shfl_sync(0xFFFFFFFFu, scv, b0.x);
        f.y = __shfl_sync(0xFFFFFFFFu, scv, b0.y);
        f.z = __shfl_sync(0xFFFFFFFFu, scv, b0.z);
        f.w = __shfl_sync(0xFFFFFFFFu, scv, b0.w); fo[i0 + 64] = f;
        f.x = __shfl_sync(0xFFFFFFFFu, scv, b1v.x);
        f.y = __shfl_sync(0xFFFFFFFFu, scv, b1v.y);
        f.z = __shfl_sync(0xFFFFFFFFu, scv, b1v.z);
        f.w = __shfl_sync(0xFFFFFFFFu, scv, b1v.w); fo[i0 + 65] = f;
    }

    const size_t obase = (size_t)row * KK;
    const int pa0 = w * 512 + lane * 8;            // first token, segment 0
    const int pb0 = pa0 + 256;                     // first token, segment 1

    if (!tie) {
        // ---- fast path: register-only ranked scatter ----
        const int ta[8] = {a0.x, a0.y, a0.z, a0.w, a1v.x, a1v.y, a1v.z, a1v.w};
        #pragma unroll
        for (int j = 0; j < 8; j++) {
            const int v = ta[j];
            const int r = __shfl_sync(0xFFFFFFFFu, B, v)
                        + (int)((Ea >> (10 * v)) & 1023ULL);
            Ea += 1ULL << (10 * v);
            if (r < KK) top_out[obase + r] = (float)(pa0 + j);
        }
        const int tb[8] = {b0.x, b0.y, b0.z, b0.w, b1v.x, b1v.y, b1v.z, b1v.w};
        #pragma unroll
        for (int j = 0; j < 8; j++) {
            const int v = tb[j];
            const int r = __shfl_sync(0xFFFFFFFFu, B, v)
                        + (int)((Eb >> (10 * v)) & 1023ULL);
            Eb += 1ULL << (10 * v);
            if (r < KK) top_out[obase + r] = (float)(pb0 + j);
        }
        // ---- warp-0 tail: analytic selcnt + classifier, barrier-free ----
        if (w == 0) {
            int sel = KK - b;
            sel = sel < 0 ? 0 : (sel > T ? T : sel);       // lanes 0..5 valid
            const float cnt = (float)sel * (1.0f / (float)KK);
            float acc0 = c1[lane], acc1 = c1[lane + 32];
            #pragma unroll
            for (int v = 0; v < VV; v++) {
                const float cv = __shfl_sync(0xFFFFFFFFu, cnt, v);
                acc0 = fmaf(cv, g_U[v][lane],      acc0);
                acc1 = fmaf(cv, g_U[v][lane + 32], acc1);
            }
            float s = fmaxf(acc0, 0.f) * C2[lane] + fmaxf(acc1, 0.f) * C2[lane + 32];
            #pragma unroll
            for (int o = 16; o; o >>= 1) s += __shfl_down_sync(0xFFFFFFFFu, s, o);
            if (lane == 0) out[row] = 1.f / (1.f + expf(-(s + c2[0])));
        }
    } else {
        // ---- tie path: exact lax.top_k mask semantics (dead in practice) ----
        if (tid < VV) selcnt_sm[tid] = 0;
        __syncthreads();
        int ls[VV] = {0, 0, 0, 0, 0, 0};
        const int ta[8] = {a0.x, a0.y, a0.z, a0.w, a1v.x, a1v.y, a1v.z, a1v.w};
        const int tb[8] = {b0.x, b0.y, b0.z, b0.w, b1v.x, b1v.y, b1v.z, b1v.w};
        #pragma unroll
        for (int seg = 0; seg < 2; seg++) {
            unsigned long long& E = seg ? Eb : Ea;
            const int* tk = seg ? tb : ta;
            const int p0 = seg ? pb0 : pa0;
            #pragma unroll
            for (int j = 0; j < 8; j++) {
                const int v = tk[j];
                const unsigned mv = __shfl_sync(0xFFFFFFFFu, m, v);
                int r = __shfl_sync(0xFFFFFFFFu, b, v);
                #pragma unroll
                for (int u = 0; u < VV; u++)
                    if ((mv >> u) & 1u)
                        r += __shfl_sync(0xFFFFFFFFu, wpre, u)
                           + (int)((E >> (10 * u)) & 1023ULL);
                E += 1ULL << (10 * v);
                if (r < KK) {
                    top_out[obase + r] = (float)(p0 + j);
                    #pragma unroll
                    for (int u = 0; u < VV; u++) ls[u] += (v == u);
                }
            }
        }
        #pragma unroll
        for (int u = 0; u < VV; u++) {
            #pragma unroll
            for (int o = 16; o; o >>= 1) ls[u] += __shfl_down_sync(0xFFFFFFFFu, ls[u], o);
        }
        if (lane == 0) {
            #pragma unroll
            for (int u = 0; u < VV; u++)
                if (ls[u]) atomicAdd(&selcnt_sm[u], ls[u]);
        }
        __syncthreads();
        if (tid < VV) scf_sm[tid] = (float)selcnt_sm[tid];
        __syncthreads();
        if (w == 0) {
            const float cnt = scf_sm[cls] * (1.0f / (float)KK);
            float acc0 = c1[lane], acc1 = c1[lane + 32];
            #pragma unroll
            for (int v = 0; v < VV; v++) {
                const float cv = __shfl_sync(0xFFFFFFFFu, cnt, v);
                acc0 = fmaf(cv, g_U[v][lane],      acc0);
                acc1 = fmaf(cv, g_U[v][lane + 32], acc1);
            }
            float s = fmaxf(acc0, 0.f) * C2[lane] + fmaxf(acc1, 0.f) * C2[lane + 32];
            #pragma unroll
            for (int o = 16; o; o >>= 1) s += __shfl_down_sync(0xFFFFFFFFu, s, o);
            if (lane == 0) out[row] = 1.f / (1.f + expf(-(s + c2[0])));
        }
    }

    // ---- replay-reset protocol: last row CTA clears the gate counters ----
    if (tid == 0) {
        if (atomicAdd(&g_pass, 1) == BB - 1) {
            g_pass = 0;
            g_done = 0;
        }
    }
}

// ===========================================================================
extern "C" void kernel_launch(void* const* d_in, const int* in_sizes, int n_in,
                              void* d_out, int out_size) {
    const int*   x   = (const int*)  d_in[0];
    const float* emb = (const float*)d_in[1];
    const float* W1  = (const float*)d_in[2];
    const float* b1  = (const float*)d_in[3];
    const float* W2  = (const float*)d_in[4];
    const float* b2  = (const float*)d_in[5];
    const float* W3  = (const float*)d_in[6];
    const float* b3  = (const float*)d_in[7];
    const float* A1  = (const float*)d_in[8];
    const float* a1  = (const float*)d_in[9];
    const float* A2  = (const float*)d_in[10];
    const float* a2  = (const float*)d_in[11];
    const float* C1  = (const float*)d_in[12];
    const float* c1  = (const float*)d_in[13];
    const float* C2  = (const float*)d_in[14];
    const float* c2  = (const float*)d_in[15];
    float* out = (float*)d_out;

    k_all<<<TBLK + BB, NT>>>(x, emb, W1, b1, W2, b2, W3, b3,
                             A1, a1, A2, a2, C1, c1, C2, c2, out);
}

// round 15
// speedup vs baseline: 1.1577x; 1.1058x over previous
#include <cuda_runtime.h>
#include <cstdint>

#define BB 512
#define SS 4096
#define DD 128
#define KK 409
#define VV 6
#define NT 256

// -------- global scratch (plain overwrites only; deterministic) --------
__device__ float g_sc [VV];
__device__ float g_U  [VV][64];    // U[v][n] = att_v . C1[:,n]

// ===========================================================================
// K1: 12 CTAs. blocks 0..5 -> score MLP per class; 6..11 -> attention+U.
// ===========================================================================
__global__ void __launch_bounds__(NT)
k1_tables(const float* __restrict__ emb,
          const float* __restrict__ W1, const float* __restrict__ b1,
          const float* __restrict__ W2, const float* __restrict__ b2,
          const float* __restrict__ W3, const float* __restrict__ b3,
          const float* __restrict__ A1, const float* __restrict__ a1,
          const float* __restrict__ A2, const float* __restrict__ a2,
          const float* __restrict__ C1) {
    const int tid = threadIdx.x;
    const int bid = blockIdx.x;
    __shared__ float e_s[DD];
    __shared__ float h1_s[64];
    __shared__ float h2_s[32];
    __shared__ float att_s[DD];

    const int v = (bid < VV) ? bid : bid - VV;
    if (tid < DD) e_s[tid] = emb[v * DD + tid];
    __syncthreads();

    if (bid < VV) {
        {   // h1: 4 threads/neuron, 8-way ILP
            const int n = tid >> 2, q = tid & 3;
            const int i0 = q * 32;
            float acc[8] = {0, 0, 0, 0, 0, 0, 0, 0};
            #pragma unroll
            for (int mm = 0; mm < 4; mm++)
                #pragma unroll
                for (int j = 0; j < 8; j++) {
                    const int i = i0 + mm * 8 + j;
                    acc[j] = fmaf(e_s[i], W1[i * 64 + n], acc[j]);
                }
            float s = ((acc[0] + acc[1]) + (acc[2] + acc[3]))
                    + ((acc[4] + acc[5]) + (acc[6] + acc[7]));
            s += __shfl_down_sync(0xFFFFFFFFu, s, 2);
            s += __shfl_down_sync(0xFFFFFFFFu, s, 1);
            if (q == 0) h1_s[n] = fmaxf(s + b1[n], 0.f);
        }
        __syncthreads();
        {   // h2: 8 threads/neuron
            const int n = tid >> 3, r = tid & 7;
            float acc[8];
            #pragma unroll
            for (int j = 0; j < 8; j++) {
                const int i = r + 8 * j;
                acc[j] = h1_s[i] * W2[i * 32 + n];
            }
            float s = ((acc[0] + acc[1]) + (acc[2] + acc[3]))
                    + ((acc[4] + acc[5]) + (acc[6] + acc[7]));
            s += __shfl_down_sync(0xFFFFFFFFu, s, 4);
            s += __shfl_down_sync(0xFFFFFFFFu, s, 2);
            s += __shfl_down_sync(0xFFFFFFFFu, s, 1);
            if (r == 0) h2_s[n] = fmaxf(s + b2[n], 0.f);
        }
        __syncthreads();
        if (tid < 32) {
            float s = h2_s[tid] * W3[tid];
            #pragma unroll
            for (int o = 16; o; o >>= 1) s += __shfl_down_sync(0xFFFFFFFFu, s, o);
            if (tid == 0) g_sc[v] = 1.f / (1.f + expf(-(s + b3[0])));
        }
    } else {
        {   // g: 4 threads/neuron
            const int n = tid >> 2, q = tid & 3;
            const int i0 = q * 32;
            float acc[8] = {0, 0, 0, 0, 0, 0, 0, 0};
            #pragma unroll
            for (int mm = 0; mm < 4; mm++)
                #pragma unroll
                for (int j = 0; j < 8; j++) {
                    const int i = i0 + mm * 8 + j;
                    acc[j] = fmaf(e_s[i], A1[i * 64 + n], acc[j]);
                }
            float s = ((acc[0] + acc[1]) + (acc[2] + acc[3]))
                    + ((acc[4] + acc[5]) + (acc[6] + acc[7]));
            s += __shfl_down_sync(0xFFFFFFFFu, s, 2);
            s += __shfl_down_sync(0xFFFFFFFFu, s, 1);
            if (q == 0) h1_s[n] = fmaxf(s + a1[n], 0.f);   // g
        }
        __syncthreads();
        {   // att: 2 threads per output dim
            const int d = tid >> 1, q = tid & 1;
            const int j0 = q * 32;
            float acc[8] = {0, 0, 0, 0, 0, 0, 0, 0};
            #pragma unroll
            for (int mm = 0; mm < 4; mm++)
                #pragma unroll
                for (int jj = 0; jj < 8; jj++) {
                    const int j = j0 + mm * 8 + jj;
                    acc[jj] = fmaf(h1_s[j], A2[j * DD + d], acc[jj]);
                }
            float s = ((acc[0] + acc[1]) + (acc[2] + acc[3]))
                    + ((acc[4] + acc[5]) + (acc[6] + acc[7]));
            s += __shfl_down_sync(0xFFFFFFFFu, s, 1);
            if (q == 0) att_s[d] = s + a2[d];
        }
        __syncthreads();
        {   // U[v][n] = att . C1[:,n]
            const int n = tid >> 2, q = tid & 3;
            const int i0 = q * 32;
            float acc[8] = {0, 0, 0, 0, 0, 0, 0, 0};
            #pragma unroll
            for (int mm = 0; mm < 4; mm++)
                #pragma unroll
                for (int j = 0; j < 8; j++) {
                    const int i = i0 + mm * 8 + j;
                    acc[j] = fmaf(att_s[i], C1[i * 64 + n], acc[j]);
                }
            float s = ((acc[0] + acc[1]) + (acc[2] + acc[3]))
                    + ((acc[4] + acc[5]) + (acc[6] + acc[7]));
            s += __shfl_down_sync(0xFFFFFFFFu, s, 2);
            s += __shfl_down_sync(0xFFFFFFFFu, s, 1);
            if (q == 0) g_U[v][n] = s;
        }
    }
}

// ===========================================================================
// K2: one CTA per row. Warp w owns tokens [w*512,(w+1)*512) as two position-
// ordered 256-token segments; lane owns 8 consecutive tokens per segment.
// fs writes issue BEFORE the barrier; scatter loop is shfl-free via the
// base-folded packed prefix (clamped to K: exact for selected ranks).
// ===========================================================================
__global__ void __launch_bounds__(NT, 4)
k2_row(const int* __restrict__ x,
       const float* __restrict__ c1, const float* __restrict__ C2,
       const float* __restrict__ c2, float* __restrict__ out) {
    const int row = blockIdx.x;
    const int tid = threadIdx.x;
    const int w = tid >> 5, lane = tid & 31;
    const int cls = (lane < VV) ? lane : 0;

    __shared__ unsigned long long wtot_s[8];
    __shared__ int   selcnt_sm[VV];                // tie path only
    __shared__ float scf_sm[VV];                   // tie path only

    float* __restrict__ top_out = out + BB;
    float* __restrict__ fs_out  = out + BB + (size_t)BB * KK;

    // scores are ready (kernel boundary) — 6 hot addresses, broadcast loads
    const float scv = g_sc[cls];

    // ---- loads: lane owns 8 consecutive tokens per segment (2 int4) ----
    const int4* rp = reinterpret_cast<const int4*>(x + (size_t)row * SS);
    const int i0 = w * 128 + lane * 2;             // int4 index, segment 0
    const int4 a0 = rp[i0];
    const int4 a1v = rp[i0 + 1];
    const int4 b0 = rp[i0 + 64];                   // segment 1 (+256 tokens)
    const int4 b1v = rp[i0 + 65];

    // ---- packed per-thread counts (10 bits/class) ----
    unsigned long long ca = 0, cb = 0;
    ca += 1ULL << (10 * a0.x);  ca += 1ULL << (10 * a0.y);
    ca += 1ULL << (10 * a0.z);  ca += 1ULL << (10 * a0.w);
    ca += 1ULL << (10 * a1v.x); ca += 1ULL << (10 * a1v.y);
    ca += 1ULL << (10 * a1v.z); ca += 1ULL << (10 * a1v.w);
    cb += 1ULL << (10 * b0.x);  cb += 1ULL << (10 * b0.y);
    cb += 1ULL << (10 * b0.z);  cb += 1ULL << (10 * b0.w);
    cb += 1ULL << (10 * b1v.x); cb += 1ULL << (10 * b1v.y);
    cb += 1ULL << (10 * b1v.z); cb += 1ULL << (10 * b1v.w);

    // ---- fs writes (LUT via shfl), issued before any barrier ----
    {
        float4* fo = reinterpret_cast<float4*>(fs_out + (size_t)row * SS);
        float4 f;
        f.x = __shfl_sync(0xFFFFFFFFu, scv, a0.x);
        f.y = __shfl_sync(0xFFFFFFFFu, scv, a0.y);
        f.z = __shfl_sync(0xFFFFFFFFu, scv, a0.z);
        f.w = __shfl_sync(0xFFFFFFFFu, scv, a0.w); fo[i0] = f;
        f.x = __shfl_sync(0xFFFFFFFFu, scv, a1v.x);
        f.y = __shfl_sync(0xFFFFFFFFu, scv, a1v.y);
        f.z = __shfl_sync(0xFFFFFFFFu, scv, a1v.z);
        f.w = __shfl_sync(0xFFFFFFFFu, scv, a1v.w); fo[i0 + 1] = f;
        f.x = __shfl_sync(0xFFFFFFFFu, scv, b0.x);
        f.y = __shfl_sync(0xFFFFFFFFu, scv, b0.y);
        f.z = __shfl_sync(0xFFFFFFFFu, scv, b0.z);
        f.w = __shfl_sync(0xFFFFFFFFu, scv, b0.w); fo[i0 + 64] = f;
        f.x = __shfl_sync(0xFFFFFFFFu, scv, b1v.x);
        f.y = __shfl_sync(0xFFFFFFFFu, scv, b1v.y);
        f.z = __shfl_sync(0xFFFFFFFFu, scv, b1v.z);
        f.w = __shfl_sync(0xFFFFFFFFu, scv, b1v.w); fo[i0 + 65] = f;
    }

    // ---- 2 interleaved inclusive warp scans ----
    unsigned long long ia = ca, ib = cb;
    #pragma unroll
    for (int off = 1; off < 32; off <<= 1) {
        const unsigned long long na = __shfl_up_sync(0xFFFFFFFFu, ia, off);
        const unsigned long long nb = __shfl_up_sync(0xFFFFFFFFu, ib, off);
        if (lane >= off) { ia += na; ib += nb; }
    }
    const unsigned long long seg0t = __shfl_sync(0xFFFFFFFFu, ia, 31);
    unsigned long long Ea = ia - ca;               // excl prefix, segment 0
    unsigned long long Eb = (ib - cb) + seg0t;     // excl prefix, segment 1
    if (lane == 31) wtot_s[w] = ia + ib;           // warp packed totals
    __syncthreads();

    // ---- per-warp lanes 0..5: class totals, warp prefix, base, eq-mask ----
    int T = 0, wpre = 0;
    #pragma unroll
    for (int i = 0; i < 8; i++) {
        const int e = (int)((wtot_s[i] >> (10 * cls)) & 1023ULL);
        T += e;
        if (i < w) wpre += e;
    }
    int b = 0; unsigned m = 0;
    #pragma unroll
    for (int u = 0; u < VV; u++) {
        const int   tu = __shfl_sync(0xFFFFFFFFu, T,   u);
        const float su = __shfl_sync(0xFFFFFFFFu, scv, u);
        if (su > scv) b += tu;
        if (su == scv) m |= 1u << u;
    }
    const bool tie =
        __ballot_sync(0xFFFFFFFFu, (lane < VV) && (m != (1u << lane))) != 0;

    const size_t obase = (size_t)row * KK;
    const int pa0 = w * 512 + lane * 8;
    const int pb0 = pa0 + 256;

    if (!tie) {
        // ---- fold clamped base into the packed prefix (shfl-free scatter) --
        // Bc = min(B, K): exact for B<K; B>=K keeps rank>=K (skipped) and
        // bounds each field to 409+512=921 < 1024 (no cross-field carry).
        const int B = b + wpre;
        const int Bc = (B < KK) ? B : KK;
        unsigned long long Bp = 0;
        #pragma unroll
        for (int u = 0; u < VV; u++)
            Bp |= (unsigned long long)__shfl_sync(0xFFFFFFFFu, Bc, u) << (10 * u);
        Ea += Bp; Eb += Bp;

        const int ta[8] = {a0.x, a0.y, a0.z, a0.w, a1v.x, a1v.y, a1v.z, a1v.w};
        #pragma unroll
        for (int j = 0; j < 8; j++) {
            const int sh = 10 * ta[j];
            const int r = (int)((Ea >> sh) & 1023ULL);
            Ea += 1ULL << sh;
            if (r < KK) top_out[obase + r] = (float)(pa0 + j);
        }
        const int tb[8] = {b0.x, b0.y, b0.z, b0.w, b1v.x, b1v.y, b1v.z, b1v.w};
        #pragma unroll
        for (int j = 0; j < 8; j++) {
            const int sh = 10 * tb[j];
            const int r = (int)((Eb >> sh) & 1023ULL);
            Eb += 1ULL << sh;
            if (r < KK) top_out[obase + r] = (float)(pb0 + j);
        }
        // ---- warp-0 tail: analytic selcnt + classifier, barrier-free ----
        if (w == 0) {
            int sel = KK - b;
            sel = sel < 0 ? 0 : (sel > T ? T : sel);       // lanes 0..5 valid
            const float cnt = (float)sel * (1.0f / (float)KK);
            float acc0 = c1[lane], acc1 = c1[lane + 32];
            #pragma unroll
            for (int v = 0; v < VV; v++) {
                const float cv = __shfl_sync(0xFFFFFFFFu, cnt, v);
                acc0 = fmaf(cv, g_U[v][lane],      acc0);
                acc1 = fmaf(cv, g_U[v][lane + 32], acc1);
            }
            float s = fmaxf(acc0, 0.f) * C2[lane] + fmaxf(acc1, 0.f) * C2[lane + 32];
            #pragma unroll
            for (int o = 16; o; o >>= 1) s += __shfl_down_sync(0xFFFFFFFFu, s, o);
            if (lane == 0) out[row] = 1.f / (1.f + expf(-(s + c2[0])));
        }
    } else {
        // ---- tie path: exact lax.top_k mask semantics (dead in practice) ----
        if (tid < VV) selcnt_sm[tid] = 0;
        __syncthreads();
        int ls[VV] = {0, 0, 0, 0, 0, 0};
        const int ta[8] = {a0.x, a0.y, a0.z, a0.w, a1v.x, a1v.y, a1v.z, a1v.w};
        const int tb[8] = {b0.x, b0.y, b0.z, b0.w, b1v.x, b1v.y, b1v.z, b1v.w};
        #pragma unroll
        for (int seg = 0; seg < 2; seg++) {
            unsigned long long& E = seg ? Eb : Ea;
            const int* tk = seg ? tb : ta;
            const int p0 = seg ? pb0 : pa0;
            #pragma unroll
            for (int j = 0; j < 8; j++) {
                const int v = tk[j];
                const unsigned mv = __shfl_sync(0xFFFFFFFFu, m, v);
                int r = __shfl_sync(0xFFFFFFFFu, b, v);
                #pragma unroll
                for (int u = 0; u < VV; u++)
                    if ((mv >> u) & 1u)
                        r += __shfl_sync(0xFFFFFFFFu, wpre, u)
                           + (int)((E >> (10 * u)) & 1023ULL);
                E += 1ULL << (10 * v);
                if (r < KK) {
                    top_out[obase + r] = (float)(p0 + j);
                    #pragma unroll
                    for (int u = 0; u < VV; u++) ls[u] += (v == u);
                }
            }
        }
        #pragma unroll
        for (int u = 0; u < VV; u++) {
            #pragma unroll
            for (int o = 16; o; o >>= 1) ls[u] += __shfl_down_sync(0xFFFFFFFFu, ls[u], o);
        }
        if (lane == 0) {
            #pragma unroll
            for (int u = 0; u < VV; u++)
                if (ls[u]) atomicAdd(&selcnt_sm[u], ls[u]);
        }
        __syncthreads();
        if (tid < VV) scf_sm[tid] = (float)selcnt_sm[tid];
        __syncthreads();
        if (w == 0) {
            const float cnt = scf_sm[cls] * (1.0f / (float)KK);
            float acc0 = c1[lane], acc1 = c1[lane + 32];
            #pragma unroll
            for (int v = 0; v < VV; v++) {
                const float cv = __shfl_sync(0xFFFFFFFFu, cnt, v);
                acc0 = fmaf(cv, g_U[v][lane],      acc0);
                acc1 = fmaf(cv, g_U[v][lane + 32], acc1);
            }
            float s = fmaxf(acc0, 0.f) * C2[lane] + fmaxf(acc1, 0.f) * C2[lane + 32];
            #pragma unroll
            for (int o = 16; o; o >>= 1) s += __shfl_down_sync(0xFFFFFFFFu, s, o);
            if (lane == 0) out[row] = 1.f / (1.f + expf(-(s + c2[0])));
        }
    }
}

// ===========================================================================
extern "C" void kernel_launch(void* const* d_in, const int* in_sizes, int n_in,
                              void* d_out, int out_size) {
    const int*   x   = (const int*)  d_in[0];
    const float* emb = (const float*)d_in[1];
    const float* W1  = (const float*)d_in[2];
    const float* b1  = (const float*)d_in[3];
    const float* W2  = (const float*)d_in[4];
    const float* b2  = (const float*)d_in[5];
    const float* W3  = (const float*)d_in[6];
    const float* b3  = (const float*)d_in[7];
    const float* A1  = (const float*)d_in[8];
    const float* a1  = (const float*)d_in[9];
    const float* A2  = (const float*)d_in[10];
    const float* a2  = (const float*)d_in[11];
    const float* C1  = (const float*)d_in[12];
    const float* c1  = (const float*)d_in[13];
    const float* C2  = (const float*)d_in[14];
    const float* c2  = (const float*)d_in[15];
    float* out = (float*)d_out;

    k1_tables<<<2 * VV, NT>>>(emb, W1, b1, W2, b2, W3, b3, A1, a1, A2, a2, C1);
    k2_row<<<BB, NT>>>(x, c1, C2, c2, out);
}